// round 6
// baseline (speedup 1.0000x reference)
#include <cuda_runtime.h>
#include <cstdint>

#define NN 100000
#define FF 32
#define DD 3
#define OO 32
#define EE 1600000
#define NPAD 102400          // 400 * 256, padded node count for scan
#define SCAN_BLOCKS 400

__device__ float  g_mu_t[DD * FF];     // [d][f]
__device__ float  g_c_t[DD * FF];      // [d][f] = -0.5*log2(e)/(1e-14+sigma^2)
__device__ int    g_is64;
__device__ int    g_count[NPAD];       // per-row edge counts
__device__ int    g_rowstart[NPAD];    // exclusive prefix sum
__device__ int    g_cursor[NPAD];      // scatter cursors
__device__ int    g_bsum[SCAN_BLOCKS];
__device__ int    g_bsumx[SCAN_BLOCKS];
__device__ float4 g_erec[EE];          // CSR edge records {p0,p1,p2,col}

// ---------------------------------------------------------------------------
__global__ void prep_kernel(const float* __restrict__ mu,
                            const float* __restrict__ sigma,
                            const int* __restrict__ ei32,
                            int total_elems) {
    int t = threadIdx.x;
    if (t < DD * FF) {
        int d = t / FF;
        int f = t % FF;
        float m = mu[f * DD + d];
        float s = sigma[f * DD + d];
        g_mu_t[d * FF + f] = m;
        g_c_t[d * FF + f]  = -0.5f * 1.4426950408889634f / (1e-14f + s * s);
    }
    if (t == 0) {
        // int64 little-endian, values < 2^31 => every odd 32-bit word is 0
        int all_zero = 1;
        int limit = 2 * total_elems;
        for (int i = 1; i < 257 && i < limit; i += 2) {
            if (ei32[i] != 0) { all_zero = 0; break; }
        }
        g_is64 = all_zero;
    }
}

// ---------------------------------------------------------------------------
__global__ void zero_counts() {
    int i = blockIdx.x * blockDim.x + threadIdx.x;
    if (i < NPAD) g_count[i] = 0;
}

// ---------------------------------------------------------------------------
// Histogram of destination rows
// ---------------------------------------------------------------------------
__global__ void hist_kernel(const int* __restrict__ ei32, int E) {
    const int is64 = g_is64;
    int stride = gridDim.x * blockDim.x;
    for (int e = blockIdx.x * blockDim.x + threadIdx.x; e < E; e += stride) {
        int r = is64 ? ei32[2 * (size_t)e] : ei32[e];
        atomicAdd(&g_count[r], 1);
    }
}

// ---------------------------------------------------------------------------
// 3-phase exclusive scan over NPAD counters
// ---------------------------------------------------------------------------
__global__ void scanA_kernel() {
    __shared__ int s[256];
    int tid = threadIdx.x;
    int i = blockIdx.x * 256 + tid;
    int v = g_count[i];
    s[tid] = v;
    __syncthreads();
#pragma unroll
    for (int off = 1; off < 256; off <<= 1) {
        int t = (tid >= off) ? s[tid - off] : 0;
        __syncthreads();
        s[tid] += t;
        __syncthreads();
    }
    g_rowstart[i] = s[tid] - v;          // exclusive
    if (tid == 255) g_bsum[blockIdx.x] = s[255];
}

__global__ void scanB_kernel() {
    __shared__ int s[512];
    int tid = threadIdx.x;
    int v = (tid < SCAN_BLOCKS) ? g_bsum[tid] : 0;
    s[tid] = v;
    __syncthreads();
#pragma unroll
    for (int off = 1; off < 512; off <<= 1) {
        int t = (tid >= off) ? s[tid - off] : 0;
        __syncthreads();
        s[tid] += t;
        __syncthreads();
    }
    if (tid < SCAN_BLOCKS) g_bsumx[tid] = s[tid] - v;
}

__global__ void scanC_kernel() {
    int tid = threadIdx.x;
    int i = blockIdx.x * 256 + tid;
    int v = g_rowstart[i] + g_bsumx[blockIdx.x];
    g_rowstart[i] = v;
    g_cursor[i] = v;
}

// ---------------------------------------------------------------------------
// Scatter edges into CSR order: record = {p0, p1, p2, bitcast(col)}
// ---------------------------------------------------------------------------
__global__ void scatter_kernel(const int* __restrict__ ei32,
                               const float* __restrict__ pseudo,
                               int E) {
    const int is64 = g_is64;
    int stride = gridDim.x * blockDim.x;
    for (int e = blockIdx.x * blockDim.x + threadIdx.x; e < E; e += stride) {
        int r, c;
        if (is64) {
            r = ei32[2 * (size_t)e];
            c = ei32[2 * ((size_t)E + e)];
        } else {
            r = ei32[e];
            c = ei32[(size_t)E + e];
        }
        float p0 = pseudo[(size_t)e * 3 + 0];
        float p1 = pseudo[(size_t)e * 3 + 1];
        float p2 = pseudo[(size_t)e * 3 + 2];
        int pos = atomicAdd(&g_cursor[r], 1);
        g_erec[pos] = make_float4(p0, p1, p2, __int_as_float(c));
    }
}

// ---------------------------------------------------------------------------
// Fused pull + linear: warp per node, lane = feature channel.
// Accumulate gaussian-weighted neighbor features in registers (no atomics),
// then apply out[n,o] = b[o] + sum_f acc[f] * W[o,f] in-warp.
// ---------------------------------------------------------------------------
__global__ void __launch_bounds__(256) pull_linear_kernel(
    const float* __restrict__ x,
    const float* __restrict__ W,
    const float* __restrict__ b,
    float* __restrict__ out,
    int N) {
    __shared__ float Ws[FF][FF + 1];
    __shared__ float bs[OO];

    const int tid = threadIdx.x;
    for (int i = tid; i < FF * OO; i += blockDim.x)
        Ws[i >> 5][i & 31] = W[i];
    if (tid < OO) bs[tid] = b[tid];
    __syncthreads();

    const int lane = tid & 31;
    const unsigned FULL = 0xffffffffu;

    // per-lane gaussian params (lane = feature)
    const float mu0 = g_mu_t[0 * FF + lane];
    const float mu1 = g_mu_t[1 * FF + lane];
    const float mu2 = g_mu_t[2 * FF + lane];
    const float c0  = g_c_t[0 * FF + lane];
    const float c1  = g_c_t[1 * FF + lane];
    const float c2  = g_c_t[2 * FF + lane];

    // per-lane W row (lane = output channel)
    float w[FF];
#pragma unroll
    for (int f = 0; f < FF; f++) w[f] = Ws[lane][f];
    const float bias = bs[lane];

    const int warp = (blockIdx.x * blockDim.x + tid) >> 5;
    const int nwarps = (gridDim.x * blockDim.x) >> 5;

    for (int n = warp; n < N; n += nwarps) {
        const int start = g_rowstart[n];
        const int cnt   = g_count[n];

        float acc = 0.f;
        for (int base = 0; base < cnt; base += 16) {
            // lanes 0-15 cooperatively load up to 16 records (LDG.128 each)
            float4 rec = make_float4(0.f, 0.f, 0.f, 0.f);
            if (lane < 16 && base + lane < cnt)
                rec = g_erec[start + base + lane];
            int m = min(16, cnt - base);
            for (int j = 0; j < m; j++) {
                float p0 = __shfl_sync(FULL, rec.x, j);
                float p1 = __shfl_sync(FULL, rec.y, j);
                float p2 = __shfl_sync(FULL, rec.z, j);
                int   c  = __float_as_int(__shfl_sync(FULL, rec.w, j));

                float xv = x[(size_t)c * FF + lane];   // coalesced 128B gather
                float d0 = p0 - mu0, d1 = p1 - mu1, d2 = p2 - mu2;
                float lw = d0 * d0 * c0 + d1 * d1 * c1 + d2 * d2 * c2;
                acc += exp2f(lw) * xv;
            }
        }

        // in-warp linear transform of acc
        float s0 = bias, s1 = 0.f, s2 = 0.f, s3 = 0.f;
#pragma unroll
        for (int f = 0; f < FF; f += 4) {
            s0 += __shfl_sync(FULL, acc, f + 0) * w[f + 0];
            s1 += __shfl_sync(FULL, acc, f + 1) * w[f + 1];
            s2 += __shfl_sync(FULL, acc, f + 2) * w[f + 2];
            s3 += __shfl_sync(FULL, acc, f + 3) * w[f + 3];
        }
        out[(size_t)n * OO + lane] = (s0 + s1) + (s2 + s3);
    }
}

// ---------------------------------------------------------------------------
extern "C" void kernel_launch(void* const* d_in, const int* in_sizes, int n_in,
                              void* d_out, int out_size) {
    const float* x   = (const float*)d_in[0];
    const int*   ei  = (const int*)d_in[1];
    const float* ps  = (const float*)d_in[2];
    const float* mu  = (const float*)d_in[3];
    const float* sg  = (const float*)d_in[4];
    const float* W   = (const float*)d_in[5];
    const float* b   = (const float*)d_in[6];
    float*       out = (float*)d_out;

    const int E = in_sizes[1] / 2;
    const int N = in_sizes[0] / FF;

    prep_kernel<<<1, 128>>>(mu, sg, ei, in_sizes[1]);
    zero_counts<<<NPAD / 256, 256>>>();
    hist_kernel<<<2048, 256>>>(ei, E);
    scanA_kernel<<<SCAN_BLOCKS, 256>>>();
    scanB_kernel<<<1, 512>>>();
    scanC_kernel<<<SCAN_BLOCKS, 256>>>();
    scatter_kernel<<<2048, 256>>>(ei, ps, E);
    pull_linear_kernel<<<148 * 8, 256>>>(x, W, b, out, N);
}

// round 7
// speedup vs baseline: 2.7353x; 2.7353x over previous
#include <cuda_runtime.h>
#include <cstdint>

#define NN 100000
#define FF 32
#define DD 3
#define OO 32

__device__ float g_accum[NN * FF];
__device__ float g_mu_t[DD * FF];   // [d][f]
__device__ float g_c_t[DD * FF];    // [d][f] = -0.5*log2(e)/(1e-14+sigma^2)
__device__ int   g_is64;

// ---------------------------------------------------------------------------
// Merged zero + prep: all blocks zero the accumulator; block 0 also
// transposes params and probes the edge dtype.
// ---------------------------------------------------------------------------
__global__ void prep_zero_kernel(const float* __restrict__ mu,
                                 const float* __restrict__ sigma,
                                 const int* __restrict__ ei32,
                                 int total_elems) {
    int i = blockIdx.x * blockDim.x + threadIdx.x;
    int total4 = (NN * FF) / 4;
    float4 z = make_float4(0.f, 0.f, 0.f, 0.f);
    float4* p = reinterpret_cast<float4*>(g_accum);
    for (int k = i; k < total4; k += gridDim.x * blockDim.x) p[k] = z;

    if (blockIdx.x == 0) {
        int t = threadIdx.x;
        if (t < DD * FF) {
            int d = t / FF;
            int f = t % FF;
            float m = mu[f * DD + d];
            float s = sigma[f * DD + d];
            g_mu_t[d * FF + f] = m;
            g_c_t[d * FF + f]  = -0.5f * 1.4426950408889634f / (1e-14f + s * s);
        }
        if (t == 0) {
            // int64 little-endian, values < 2^31 => every odd 32-bit word is 0
            int all_zero = 1;
            int limit = 2 * total_elems;
            for (int k = 1; k < 257 && k < limit; k += 2) {
                if (ei32[k] != 0) { all_zero = 0; break; }
            }
            g_is64 = all_zero;
        }
    }
}

// ---------------------------------------------------------------------------
// Edge kernel (R5 winner, unchanged): 8 edges per warp-iteration,
// cooperative index/pseudo loads, two independent gather->RED chains,
// red.global.add.v4.f32 scatter.
// ---------------------------------------------------------------------------
__global__ void __launch_bounds__(256) edge_kernel(
    const float* __restrict__ x,
    const void* __restrict__ edge_index,
    const float* __restrict__ pseudo,
    int E) {
    const int lane  = threadIdx.x & 31;
    const int g     = lane >> 3;
    const int q     = lane & 7;
    const int fbase = q * 4;
    const int warp  = (blockIdx.x * blockDim.x + threadIdx.x) >> 5;
    const int nwarps = (gridDim.x * blockDim.x) >> 5;
    const unsigned FULL = 0xffffffffu;

    const int is64 = g_is64;
    const int* __restrict__ ei32 = (const int*)edge_index;
    const long long* __restrict__ ei64 = (const long long*)edge_index;

    float mu0[4], mu1[4], mu2[4], c0[4], c1[4], c2[4];
#pragma unroll
    for (int j = 0; j < 4; j++) {
        mu0[j] = g_mu_t[0 * FF + fbase + j];
        mu1[j] = g_mu_t[1 * FF + fbase + j];
        mu2[j] = g_mu_t[2 * FF + fbase + j];
        c0[j]  = g_c_t[0 * FF + fbase + j];
        c1[j]  = g_c_t[1 * FF + fbase + j];
        c2[j]  = g_c_t[2 * FF + fbase + j];
    }

    for (long long eb = (long long)warp * 8; eb < E; eb += (long long)nwarps * 8) {
        int idx = 0;
        {
            long long epos = eb + (lane & 7);
            if (lane < 16 && epos < E) {
                long long a = (lane < 8) ? epos : epos + (long long)E;
                idx = is64 ? (int)ei64[a] : ei32[a];
            }
        }
        float pv = 0.f;
        {
            long long ppos = eb * 3 + lane;
            if (lane < 24 && ppos < (long long)E * 3) pv = pseudo[ppos];
        }

        const int rA = __shfl_sync(FULL, idx, g);
        const int rB = __shfl_sync(FULL, idx, 4 + g);
        const int cA = __shfl_sync(FULL, idx, 8 + g);
        const int cB = __shfl_sync(FULL, idx, 12 + g);
        const float p0A = __shfl_sync(FULL, pv, 3 * g + 0);
        const float p1A = __shfl_sync(FULL, pv, 3 * g + 1);
        const float p2A = __shfl_sync(FULL, pv, 3 * g + 2);
        const float p0B = __shfl_sync(FULL, pv, 12 + 3 * g + 0);
        const float p1B = __shfl_sync(FULL, pv, 12 + 3 * g + 1);
        const float p2B = __shfl_sync(FULL, pv, 12 + 3 * g + 2);

        const bool aval = (eb + g) < E;
        const bool bval = (eb + 4 + g) < E;

        float4 xa = make_float4(0.f, 0.f, 0.f, 0.f);
        float4 xb = make_float4(0.f, 0.f, 0.f, 0.f);
        if (aval) xa = *reinterpret_cast<const float4*>(x + (size_t)cA * FF + fbase);
        if (bval) xb = *reinterpret_cast<const float4*>(x + (size_t)cB * FF + fbase);

        float xaj[4] = {xa.x, xa.y, xa.z, xa.w};
        float xbj[4] = {xb.x, xb.y, xb.z, xb.w};
        float vA[4], vB[4];
#pragma unroll
        for (int j = 0; j < 4; j++) {
            float d0 = p0A - mu0[j], d1 = p1A - mu1[j], d2 = p2A - mu2[j];
            float lw = d0 * d0 * c0[j] + d1 * d1 * c1[j] + d2 * d2 * c2[j];
            vA[j] = exp2f(lw) * xaj[j];
        }
#pragma unroll
        for (int j = 0; j < 4; j++) {
            float d0 = p0B - mu0[j], d1 = p1B - mu1[j], d2 = p2B - mu2[j];
            float lw = d0 * d0 * c0[j] + d1 * d1 * c1[j] + d2 * d2 * c2[j];
            vB[j] = exp2f(lw) * xbj[j];
        }

        if (aval) {
            float* dst = g_accum + (size_t)rA * FF + fbase;
            asm volatile("red.global.add.v4.f32 [%0], {%1, %2, %3, %4};"
                         :: "l"(dst), "f"(vA[0]), "f"(vA[1]), "f"(vA[2]), "f"(vA[3])
                         : "memory");
        }
        if (bval) {
            float* dst = g_accum + (size_t)rB * FF + fbase;
            asm volatile("red.global.add.v4.f32 [%0], {%1, %2, %3, %4};"
                         :: "l"(dst), "f"(vB[0]), "f"(vB[1]), "f"(vB[2]), "f"(vB[3])
                         : "memory");
        }
    }
}

// ---------------------------------------------------------------------------
// Linear epilogue v4: smem-tile broadcast instead of SHFL.
// Warp handles 32 nodes: stage accum rows into padded smem (coalesced f4),
// then each lane (= output channel) computes 32 dot products via broadcast
// LDS.128 reads + register-resident W row. No SHFL in the hot loop.
// ---------------------------------------------------------------------------
__global__ void __launch_bounds__(256) linear_kernel(
    const float* __restrict__ W,
    const float* __restrict__ b,
    float* __restrict__ out,
    int N) {
    __shared__ float Ws[FF][FF + 1];
    __shared__ float bs[OO];
    __shared__ float As[8][32][36];   // [warp][node][feat], stride 36 (16B-aligned, conflict-free)

    const int tid = threadIdx.x;
    for (int i = tid; i < FF * OO; i += 256)
        Ws[i >> 5][i & 31] = W[i];
    if (tid < OO) bs[tid] = b[tid];
    __syncthreads();

    const int lane = tid & 31;
    const int w    = tid >> 5;

    float wreg[FF];
#pragma unroll
    for (int f = 0; f < FF; f++) wreg[f] = Ws[lane][f];
    const float bias = bs[lane];

    const int node0 = (blockIdx.x * 8 + w) * 32;
    if (node0 >= N) return;

    // stage: 32 nodes x 32 floats = 256 float4, coalesced
#pragma unroll
    for (int r = 0; r < 8; r++) {
        int idx = r * 32 + lane;          // float4 index 0..255
        int n   = idx >> 3;
        int f4  = idx & 7;
        float4 v = make_float4(0.f, 0.f, 0.f, 0.f);
        if (node0 + n < N)
            v = *reinterpret_cast<const float4*>(g_accum + (size_t)(node0 + n) * FF + f4 * 4);
        *reinterpret_cast<float4*>(&As[w][n][f4 * 4]) = v;
    }
    __syncwarp();

    const int nmax = min(32, N - node0);
#pragma unroll 4
    for (int n = 0; n < 32; n++) {
        if (n >= nmax) break;
        float s0 = bias, s1 = 0.f, s2 = 0.f, s3 = 0.f;
#pragma unroll
        for (int f4 = 0; f4 < 8; f4++) {
            float4 a = *reinterpret_cast<const float4*>(&As[w][n][f4 * 4]);  // broadcast LDS.128
            s0 += a.x * wreg[f4 * 4 + 0];
            s1 += a.y * wreg[f4 * 4 + 1];
            s2 += a.z * wreg[f4 * 4 + 2];
            s3 += a.w * wreg[f4 * 4 + 3];
        }
        out[(size_t)(node0 + n) * OO + lane] = (s0 + s1) + (s2 + s3);  // coalesced
    }
}

// ---------------------------------------------------------------------------
extern "C" void kernel_launch(void* const* d_in, const int* in_sizes, int n_in,
                              void* d_out, int out_size) {
    const float* x   = (const float*)d_in[0];
    const void*  ei  = d_in[1];
    const float* ps  = (const float*)d_in[2];
    const float* mu  = (const float*)d_in[3];
    const float* sg  = (const float*)d_in[4];
    const float* W   = (const float*)d_in[5];
    const float* b   = (const float*)d_in[6];
    float*       out = (float*)d_out;

    const int E = in_sizes[1] / 2;
    const int N = in_sizes[0] / FF;

    prep_zero_kernel<<<800, 256>>>(mu, sg, (const int*)ei, in_sizes[1]);
    edge_kernel<<<148 * 8, 256>>>(x, ei, ps, E);
    linear_kernel<<<(N + 255) / 256, 256>>>(W, b, out, N);
}